// round 5
// baseline (speedup 1.0000x reference)
#include <cuda_runtime.h>

#define S   2048
#define F   512
#define B   32
#define RAD 12
#define KW  25
#define TS  32   // outputs per thread along s in the smoothing kernel

// ---------------- scratch (device globals: no allocations allowed) ----------
__device__ float g_smooth[B * S * F];   // 128 MB smoothed tensor
__device__ int   g_i0[S];
__device__ float g_frac[S];

// Gaussian taps (sigma=3, radius=12, normalized) — compile-time immediates
// (fully-unrolled loops index this with constants; ptxas folds to FFMA-imm).
__device__ constexpr float KERN[KW] = {
    4.46116e-05f, 1.60100e-04f, 5.14120e-04f, 1.47730e-03f, 3.79880e-03f,
    8.74080e-03f, 1.799760e-02f, 3.316010e-02f, 5.467130e-02f, 8.065920e-02f,
    1.0648560e-01f, 1.2579790e-01f, 1.3298450e-01f, 1.2579790e-01f, 1.0648560e-01f,
    8.065920e-02f, 5.467130e-02f, 3.316010e-02f, 1.799760e-02f, 8.74080e-03f,
    3.79880e-03f, 1.47730e-03f, 5.14120e-04f, 1.60100e-04f, 4.46116e-05f
};

__device__ __forceinline__ int reflect_idx(int r) {
    // np.pad mode='symmetric': -1 -> 0, -2 -> 1, S -> S-1, ...
    if (r < 0)       r = -1 - r;
    else if (r >= S) r = 2 * S - 1 - r;
    return r;
}

// ---------------- kernel A: warp precompute + loss (1 block, 256 thr) -------
// Numerics carefully mirror the jax reference:
//  * tt = iota * fl(1/2047)            (jnp.linspace)
//  * mul/add kept separate (no FMA)    (XLA does not contract f32)
//  * 64-length dot: sequential ascending adds from 0
//  * softplus = logaddexp(w, 0) = max(w,0) + log1p(exp(-|w|))  (libdevice)
//  * cumsum  = jax associative_scan pairwise tree (NOT Hillis-Steele) —
//    this reproduces the reference's fp32 rounding pattern, which dominates
//    the second-difference smoothness loss.
#define WT 256
__global__ void __launch_bounds__(WT) warp_precompute_kernel(
        const float* __restrict__ W1,
        const float* __restrict__ b1,
        const float* __restrict__ W2,
        const float* __restrict__ b2,
        float* __restrict__ out_loss) {
    __shared__ float lev[4095];   // levels 0..11 of the scan tree (2048+1024+...+1)
    __shared__ float warps[S];
    __shared__ float red[WT];

    const int t = threadIdx.x;

    // level offsets: off[l] = start of level l (size 2048 >> l)
    int off[12];
    {
        int o = 0;
        #pragma unroll
        for (int l = 0; l < 12; l++) { off[l] = o; o += (2048 >> l); }
    }

    // ---- elementwise: sp[s] = softplus(tanh(MLP(tt[s]))) into level 0 ----
    const float delta = 1.0f / 2047.0f;   // fl(1/2047), linspace step
    for (int s = t; s < S; s += WT) {
        float tt = __fmul_rn((float)s, delta);
        if (s == S - 1) tt = 1.0f;        // linspace endpoint
        float acc = 0.0f;
        for (int j = 0; j < 64; j++) {    // sequential, ascending (dot order)
            float h = __fadd_rn(__fmul_rn(tt, W1[j]), b1[j]);
            h = fmaxf(h, 0.0f);
            acc = __fadd_rn(acc, __fmul_rn(h, W2[j]));
        }
        float w  = tanhf(__fadd_rn(acc, b2[0]));
        float sp = __fadd_rn(fmaxf(w, 0.0f), log1pf(expf(-fabsf(w))));
        lev[off[0] + s] = sp;
    }

    // ---- bottom-up: pairwise sums ----
    for (int l = 0; l < 11; l++) {
        __syncthreads();
        const float* src = lev + off[l];
        float*       dst = lev + off[l + 1];
        const int n_next = 2048 >> (l + 1);
        for (int k = t; k < n_next; k += WT)
            dst[k] = __fadd_rn(src[2 * k], src[2 * k + 1]);
    }
    __syncthreads();

    // ---- top-down: level 11 scan is itself; rebuild scans in place ----
    // S_l[2k+1] = S_{l+1}[k];  S_l[0] = L_l[0];  S_l[2k] = S_{l+1}[k-1] + L_l[2k]
    for (int l = 10; l >= 0; l--) {
        float*       Ll  = lev + off[l];
        const float* Sl1 = lev + off[l + 1];
        const int half = 2048 >> (l + 1);
        for (int k = t; k < half; k += WT) {
            float odd_val  = Sl1[k];
            float even_val = (k == 0) ? Ll[0] : __fadd_rn(Sl1[k - 1], Ll[2 * k]);
            Ll[2 * k]     = even_val;
            Ll[2 * k + 1] = odd_val;
        }
        __syncthreads();
    }
    // lev[0..2047] now holds the inclusive scan with XLA's exact rounding.

    const float T = lev[S - 1];

    for (int s = t; s < S; s += WT)
        warps[s] = __fdiv_rn(lev[s], T);
    __syncthreads();

    // interpolation tables (warps * (S-1), floor, clip, frac — same op chain)
    for (int s = t; s < S; s += WT) {
        float pos = __fmul_rn(warps[s], (float)(S - 1));
        float fi  = floorf(pos);
        fi = fminf(fmaxf(fi, 0.0f), (float)(S - 2));
        int i0 = (int)fi;
        g_i0[s]   = i0;
        g_frac[s] = __fadd_rn(pos, -fi);
    }

    // smoothness loss: diff(diff(warps)) on the stored fp32 warps values
    float lsum = 0.0f;
    for (int m = t; m < S - 2; m += WT) {
        float d1a = __fadd_rn(warps[m + 1], -warps[m]);
        float d1b = __fadd_rn(warps[m + 2], -warps[m + 1]);
        float d2  = __fadd_rn(d1b, -d1a);
        lsum = fmaf(d2, d2, lsum);
    }
    red[t] = lsum;
    __syncthreads();
    for (int o2 = WT / 2; o2 > 0; o2 >>= 1) {
        if (t < o2) red[t] += red[t + o2];
        __syncthreads();
    }
    if (t == 0) *out_loss = red[0] / (float)(S - 2);
}

// ---------------- kernel B: 25-tap Gaussian smoothing along s ----------------
// grid: (S/TS, F/128, B), block: 128 threads (thread = one f lane)
__global__ void __launch_bounds__(128) smooth_kernel(const float* __restrict__ x) {
    const int tx = threadIdx.x;
    const int f  = blockIdx.y * 128 + tx;
    const int s0 = blockIdx.x * TS;
    const int b  = blockIdx.z;

    const float* xb = x + b * (S * F) + f;

    float acc[TS];
    #pragma unroll
    for (int j = 0; j < TS; j++) acc[j] = 0.0f;

    #pragma unroll
    for (int i = 0; i < TS + KW - 1; i++) {
        const int r = reflect_idx(s0 - RAD + i);
        const float v = __ldg(xb + r * F);
        #pragma unroll
        for (int j = 0; j < TS; j++) {
            const int k = i - j;
            if (k >= 0 && k < KW)
                acc[j] = fmaf(v, KERN[k], acc[j]);   // tap is an immediate
        }
    }

    float* ob = g_smooth + b * (S * F) + f;
    #pragma unroll
    for (int j = 0; j < TS; j++) ob[(s0 + j) * F] = acc[j];
}

// ---------------- kernel C: gather + linear interp -------------------------
// grid: (S, B), block: 128 threads, float4 over F
__global__ void __launch_bounds__(128) interp_kernel(float* __restrict__ out) {
    const int s = blockIdx.x;
    const int b = blockIdx.y;
    const int t = threadIdx.x;

    const int   i0 = g_i0[s];
    const float fr = g_frac[s];
    const float om = 1.0f - fr;

    const float4* r0 = (const float4*)(g_smooth + (b * S + i0) * F);
    const float4* r1 = (const float4*)(g_smooth + (b * S + i0 + 1) * F);
    float4*       op = (float4*)out + (b * S + s) * (F / 4);

    const float4 a = r0[t];
    const float4 c = r1[t];
    float4 o;
    o.x = a.x * om + c.x * fr;
    o.y = a.y * om + c.y * fr;
    o.z = a.z * om + c.z * fr;
    o.w = a.w * om + c.w * fr;
    op[t] = o;
}

// ---------------- launch ----------------------------------------------------
extern "C" void kernel_launch(void* const* d_in, const int* in_sizes, int n_in,
                              void* d_out, int out_size) {
    const float* x  = (const float*)d_in[0];
    const float* W1 = (const float*)d_in[1];
    const float* b1 = (const float*)d_in[2];
    const float* W2 = (const float*)d_in[3];
    const float* b2 = (const float*)d_in[4];
    float* out = (float*)d_out;

    // loss scalar is the last output element
    warp_precompute_kernel<<<1, WT>>>(W1, b1, W2, b2, out + (out_size - 1));

    dim3 gridB(S / TS, F / 128, B);
    smooth_kernel<<<gridB, 128>>>(x);

    dim3 gridC(S, B);
    interp_kernel<<<gridC, 128>>>(out);
}